// round 4
// baseline (speedup 1.0000x reference)
#include <cuda_runtime.h>

// GRU autoencoder, SEQ_LEN=4096.
// e1: 1 -> 2048, e2: 2048 -> 1024 (pipelined, 1 grid-sync/step)
// d1: 1024 -> 1024 (constant input => xg precomputed), d2: 1024 -> 2048 (pipelined)
// head: 2048 -> 1

#define TT    4096
#define H1    2048     // e1 / d2 hidden
#define H2    1024     // e2 / d1 hidden
#define NBLK  148
#define NTHR  256
#define WPB   (NTHR >> 5)
#define NWARP (NBLK * WPB)

// ---------------- device scratch (allowed: static __device__ globals) ----------
__device__ float g_h1[2][H1];        // e1 state, double buffered by time parity
__device__ float g_h2[2][H2];        // e2 state
__device__ float g_hd1[2][H2];       // d1 state
__device__ float g_xgd1[3 * H2];     // constant input-gate preactivation for d1
__device__ float g_ys3[TT][H1];      // d2 outputs (also d2 state history)

__device__ __align__(128) unsigned int g_barcnt[32];   // zero-init at load; self-resetting
__device__ __align__(128) unsigned int g_bargen[32];

// ---------------- helpers -----------------------------------------------------
__device__ __forceinline__ float warp_red(float v) {
    v += __shfl_down_sync(0xffffffffu, v, 16);
    v += __shfl_down_sync(0xffffffffu, v, 8);
    v += __shfl_down_sync(0xffffffffu, v, 4);
    v += __shfl_down_sync(0xffffffffu, v, 2);
    v += __shfl_down_sync(0xffffffffu, v, 1);
    return v;
}

// Software grid barrier. All NBLK blocks are guaranteed co-resident
// (grid == NBLK <= SM count, 1 block/SM via __launch_bounds__).
__device__ __forceinline__ void gridsync() {
    __threadfence();
    __syncthreads();
    if (threadIdx.x == 0) {
        volatile unsigned int* gen = &g_bargen[0];
        unsigned int g = *gen;
        if (atomicAdd(&g_barcnt[0], 1u) == NBLK - 1) {
            g_barcnt[0] = 0;
            __threadfence();
            *gen = g + 1;
        } else {
            while (*gen == g) { }
        }
        __threadfence();
    }
    __syncthreads();
}

// 3 simultaneous dot products (r/z/n rows) against a shared-memory vector.
// Rows are contiguous fp32, vector lives in SMEM. Lane-strided float4 loads.
template <int L>
__device__ __forceinline__ void dot3(const float* __restrict__ w0,
                                     const float* __restrict__ w1,
                                     const float* __restrict__ w2,
                                     const float* __restrict__ sv,
                                     int lane, float& d0, float& d1, float& d2) {
    float a0 = 0.f, a1 = 0.f, a2 = 0.f;
#pragma unroll 4
    for (int j = 0; j < L / 128; ++j) {
        const int idx = j * 128 + lane * 4;
        const float4 v  = *reinterpret_cast<const float4*>(sv + idx);
        const float4 r0 = __ldg(reinterpret_cast<const float4*>(w0 + idx));
        const float4 r1 = __ldg(reinterpret_cast<const float4*>(w1 + idx));
        const float4 r2 = __ldg(reinterpret_cast<const float4*>(w2 + idx));
        a0 = fmaf(r0.x, v.x, a0); a0 = fmaf(r0.y, v.y, a0);
        a0 = fmaf(r0.z, v.z, a0); a0 = fmaf(r0.w, v.w, a0);
        a1 = fmaf(r1.x, v.x, a1); a1 = fmaf(r1.y, v.y, a1);
        a1 = fmaf(r1.z, v.z, a1); a1 = fmaf(r1.w, v.w, a1);
        a2 = fmaf(r2.x, v.x, a2); a2 = fmaf(r2.y, v.y, a2);
        a2 = fmaf(r2.z, v.z, a2); a2 = fmaf(r2.w, v.w, a2);
    }
    d0 = warp_red(a0);
    d1 = warp_red(a1);
    d2 = warp_red(a2);
}

__device__ __forceinline__ float sigf(float v) { return 1.f / (1.f + expf(-v)); }

// ---------------- encoder: e1 (1->2048) + e2 (2048->1024), pipelined ----------
__global__ void __launch_bounds__(NTHR, 1) gru_encoder(
    const float* __restrict__ x,
    const float* __restrict__ w1ih, const float* __restrict__ w1hh,
    const float* __restrict__ b1ih, const float* __restrict__ b1hh,
    const float* __restrict__ w2ih, const float* __restrict__ w2hh,
    const float* __restrict__ b2ih, const float* __restrict__ b2hh)
{
    __shared__ __align__(16) float s_h1[H1];   // h1(t-1) == ys1(t-1) (shared by both layers)
    __shared__ __align__(16) float s_h2[H2];   // h2(t-2)
    const int tid  = threadIdx.x;
    const int lane = tid & 31;
    const int gw   = blockIdx.x * WPB + (tid >> 5);

    // Iter t: layer1 computes h1(t) (t<TT); layer2 computes h2(t-1) (t>=1).
    // State storage parity(u) = u & 1. Zero-fill branches make replays deterministic.
    for (int t = 0; t <= TT; ++t) {
        const float* h1p = g_h1[(t + 1) & 1];   // parity of (t-1)
        for (int i = tid; i < H1; i += NTHR)
            s_h1[i] = (t == 0) ? 0.f : __ldcg(h1p + i);
        const float* h2p = g_h2[t & 1];          // parity of (t-2)
        for (int i = tid; i < H2; i += NTHR)
            s_h2[i] = (t <= 1) ? 0.f : __ldcg(h2p + i);
        __syncthreads();

        const float xt = (t < TT) ? __ldg(x + t) : 0.f;

        for (int k = gw; k < H1 + H2; k += NWARP) {
            if (k < H1) {
                if (t == TT) continue;
                const int i = k;
                float hr, hz, hn;
                dot3<H1>(w1hh + (size_t)i * H1,
                         w1hh + (size_t)(i + H1) * H1,
                         w1hh + (size_t)(i + 2 * H1) * H1,
                         s_h1, lane, hr, hz, hn);
                if (lane == 0) {
                    const float xr = fmaf(xt, __ldg(w1ih + i),          __ldg(b1ih + i));
                    const float xz = fmaf(xt, __ldg(w1ih + i + H1),     __ldg(b1ih + i + H1));
                    const float xn = fmaf(xt, __ldg(w1ih + i + 2 * H1), __ldg(b1ih + i + 2 * H1));
                    hr += __ldg(b1hh + i);
                    hz += __ldg(b1hh + i + H1);
                    hn += __ldg(b1hh + i + 2 * H1);
                    const float r = sigf(xr + hr);
                    const float z = sigf(xz + hz);
                    const float n = tanhf(xn + r * hn);
                    g_h1[t & 1][i] = (1.f - z) * n + z * s_h1[i];
                }
            } else {
                if (t == 0) continue;
                const int i = k - H1;   // e2 output index, computing h2(t-1)
                float xr, xz, xn, hr, hz, hn;
                dot3<H1>(w2ih + (size_t)i * H1,
                         w2ih + (size_t)(i + H2) * H1,
                         w2ih + (size_t)(i + 2 * H2) * H1,
                         s_h1, lane, xr, xz, xn);             // input = ys1(t-1)
                dot3<H2>(w2hh + (size_t)i * H2,
                         w2hh + (size_t)(i + H2) * H2,
                         w2hh + (size_t)(i + 2 * H2) * H2,
                         s_h2, lane, hr, hz, hn);
                if (lane == 0) {
                    xr += __ldg(b2ih + i);
                    xz += __ldg(b2ih + i + H2);
                    xn += __ldg(b2ih + i + 2 * H2);
                    hr += __ldg(b2hh + i);
                    hz += __ldg(b2hh + i + H2);
                    hn += __ldg(b2hh + i + 2 * H2);
                    const float r = sigf(xr + hr);
                    const float z = sigf(xz + hz);
                    const float n = tanhf(xn + r * hn);
                    g_h2[(t + 1) & 1][i] = (1.f - z) * n + z * s_h2[i]; // parity of (t-1)
                }
            }
        }
        gridsync();
    }
}

// ---------------- d1 constant input-gate preactivation ------------------------
// emb = final h2 = h2(TT-1), stored at parity (TT-1)&1 == 1.
__global__ void gru_xgd1(const float* __restrict__ d1ih,
                         const float* __restrict__ d1bih)
{
    const int lane = threadIdx.x & 31;
    const int gw = blockIdx.x * (blockDim.x >> 5) + (threadIdx.x >> 5);
    const int nw = gridDim.x * (blockDim.x >> 5);
    for (int j = gw; j < 3 * H2; j += nw) {
        float a = 0.f;
        const float* w = d1ih + (size_t)j * H2;
#pragma unroll 4
        for (int q = 0; q < H2 / 128; ++q) {
            const int idx = q * 128 + lane * 4;
            const float4 r = __ldg(reinterpret_cast<const float4*>(w + idx));
            float4 v;
            v.x = __ldcg(&g_h2[1][idx]);
            v.y = __ldcg(&g_h2[1][idx + 1]);
            v.z = __ldcg(&g_h2[1][idx + 2]);
            v.w = __ldcg(&g_h2[1][idx + 3]);
            a = fmaf(r.x, v.x, a); a = fmaf(r.y, v.y, a);
            a = fmaf(r.z, v.z, a); a = fmaf(r.w, v.w, a);
        }
        a = warp_red(a);
        if (lane == 0) g_xgd1[j] = a + __ldg(d1bih + j);
    }
}

// ---------------- decoder: d1 (const in ->1024) + d2 (1024->2048), pipelined --
__global__ void __launch_bounds__(NTHR, 1) gru_decoder(
    const float* __restrict__ w1hh, const float* __restrict__ b1hh,
    const float* __restrict__ w2ih, const float* __restrict__ w2hh,
    const float* __restrict__ b2ih, const float* __restrict__ b2hh)
{
    __shared__ __align__(16) float s_d1[H2];   // hd1(t-1) == ys2(t-1)
    __shared__ __align__(16) float s_y3[H1];   // ys3(t-2) == hd2 prev state
    const int tid  = threadIdx.x;
    const int lane = tid & 31;
    const int gw   = blockIdx.x * WPB + (tid >> 5);

    for (int t = 0; t <= TT; ++t) {
        const int s = t - 1;                    // d2 computes ys3[s]
        const float* d1p = g_hd1[(t + 1) & 1];
        for (int i = tid; i < H2; i += NTHR)
            s_d1[i] = (t == 0) ? 0.f : __ldcg(d1p + i);
        for (int i = tid; i < H1; i += NTHR)
            s_y3[i] = (t <= 1) ? 0.f : __ldcg(&g_ys3[s - 1][i]);
        __syncthreads();

        for (int k = gw; k < H2 + H1; k += NWARP) {
            if (k < H2) {
                if (t == TT) continue;
                const int i = k;                // d1 output, computing hd1(t)
                float hr, hz, hn;
                dot3<H2>(w1hh + (size_t)i * H2,
                         w1hh + (size_t)(i + H2) * H2,
                         w1hh + (size_t)(i + 2 * H2) * H2,
                         s_d1, lane, hr, hz, hn);
                if (lane == 0) {
                    const float xr = g_xgd1[i];             // includes bih
                    const float xz = g_xgd1[i + H2];
                    const float xn = g_xgd1[i + 2 * H2];
                    hr += __ldg(b1hh + i);
                    hz += __ldg(b1hh + i + H2);
                    hn += __ldg(b1hh + i + 2 * H2);
                    const float r = sigf(xr + hr);
                    const float z = sigf(xz + hz);
                    const float n = tanhf(xn + r * hn);
                    g_hd1[t & 1][i] = (1.f - z) * n + z * s_d1[i];
                }
            } else {
                if (t == 0) continue;
                const int i = k - H2;           // d2 output, computing ys3[s]
                float xr, xz, xn, hr, hz, hn;
                dot3<H2>(w2ih + (size_t)i * H2,
                         w2ih + (size_t)(i + H1) * H2,
                         w2ih + (size_t)(i + 2 * H1) * H2,
                         s_d1, lane, xr, xz, xn);           // input = ys2(s)
                dot3<H1>(w2hh + (size_t)i * H1,
                         w2hh + (size_t)(i + H1) * H1,
                         w2hh + (size_t)(i + 2 * H1) * H1,
                         s_y3, lane, hr, hz, hn);
                if (lane == 0) {
                    xr += __ldg(b2ih + i);
                    xz += __ldg(b2ih + i + H1);
                    xn += __ldg(b2ih + i + 2 * H1);
                    hr += __ldg(b2hh + i);
                    hz += __ldg(b2hh + i + H1);
                    hn += __ldg(b2hh + i + 2 * H1);
                    const float r = sigf(xr + hr);
                    const float z = sigf(xz + hz);
                    const float n = tanhf(xn + r * hn);
                    g_ys3[s][i] = (1.f - z) * n + z * s_y3[i];
                }
            }
        }
        gridsync();
    }
}

// ---------------- output head: out[t] = ys3[t] . out_W + out_b ----------------
__global__ void gru_output(const float* __restrict__ ow,
                           const float* __restrict__ ob,
                           float* __restrict__ out)
{
    const int lane = threadIdx.x & 31;
    const int gw = blockIdx.x * (blockDim.x >> 5) + (threadIdx.x >> 5);
    const int nw = gridDim.x * (blockDim.x >> 5);
    for (int t = gw; t < TT; t += nw) {
        float a = 0.f;
#pragma unroll 4
        for (int q = 0; q < H1 / 128; ++q) {
            const int idx = q * 128 + lane * 4;
            const float4 w = __ldg(reinterpret_cast<const float4*>(ow + idx));
            const float4 v = *reinterpret_cast<const float4*>(&g_ys3[t][idx]);
            a = fmaf(w.x, v.x, a); a = fmaf(w.y, v.y, a);
            a = fmaf(w.z, v.z, a); a = fmaf(w.w, v.w, a);
        }
        a = warp_red(a);
        if (lane == 0) out[t] = a + __ldg(ob);
    }
}

// ---------------- launch ------------------------------------------------------
extern "C" void kernel_launch(void* const* d_in, const int* in_sizes, int n_in,
                              void* d_out, int out_size) {
    const float* x      = (const float*)d_in[0];
    const float* e1_Wih = (const float*)d_in[1];
    const float* e1_Whh = (const float*)d_in[2];
    const float* e1_bih = (const float*)d_in[3];
    const float* e1_bhh = (const float*)d_in[4];
    const float* e2_Wih = (const float*)d_in[5];
    const float* e2_Whh = (const float*)d_in[6];
    const float* e2_bih = (const float*)d_in[7];
    const float* e2_bhh = (const float*)d_in[8];
    const float* d1_Wih = (const float*)d_in[9];
    const float* d1_Whh = (const float*)d_in[10];
    const float* d1_bih = (const float*)d_in[11];
    const float* d1_bhh = (const float*)d_in[12];
    const float* d2_Wih = (const float*)d_in[13];
    const float* d2_Whh = (const float*)d_in[14];
    const float* d2_bih = (const float*)d_in[15];
    const float* d2_bhh = (const float*)d_in[16];
    const float* out_W  = (const float*)d_in[17];
    const float* out_b  = (const float*)d_in[18];

    gru_encoder<<<NBLK, NTHR>>>(x, e1_Wih, e1_Whh, e1_bih, e1_bhh,
                                e2_Wih, e2_Whh, e2_bih, e2_bhh);
    gru_xgd1<<<96, 256>>>(d1_Wih, d1_bih);
    gru_decoder<<<NBLK, NTHR>>>(d1_Whh, d1_bhh, d2_Wih, d2_Whh, d2_bih, d2_bhh);
    gru_output<<<256, 256>>>(out_W, out_b, (float*)d_out);
}

// round 5
// speedup vs baseline: 1.3516x; 1.3516x over previous
#include <cuda_runtime.h>
#include <cuda_fp16.h>

// GRU autoencoder, SEQ_LEN=4096, fp16-compressed streamed weights, fp32 math.
// e1: 1 -> 2048, e2: 2048 -> 1024 (pipelined, 1 grid-sync/step)
// d1: 1024 -> 1024 (constant input => xg precomputed), d2: 1024 -> 2048 (pipelined)
// head: 2048 -> 1

#define TT    4096
#define H1    2048     // e1 / d2 hidden
#define H2    1024     // e2 / d1 hidden
#define NTHR  256
#define WPB   (NTHR >> 5)

// ---------------- device scratch ----------------------------------------------
__device__ float g_h1[2][H1];        // e1 state, double buffered by time parity
__device__ float g_h2[2][H2];        // e2 state
__device__ float g_hd1[2][H2];       // d1 state
__device__ float g_xgd1[3 * H2];     // constant input-gate preactivation for d1
__device__ float g_ys3[TT][H1];      // d2 outputs (also d2 state history)

// fp16 copies of the streamed weight matrices (converted on every launch)
__device__ __align__(16) __half c_w1hh[3 * H1 * H1];   // 25.2 MB
__device__ __align__(16) __half c_w2ih[3 * H2 * H1];   // 12.6 MB
__device__ __align__(16) __half c_w2hh[3 * H2 * H2];   //  6.3 MB
__device__ __align__(16) __half c_d1hh[3 * H2 * H2];   //  6.3 MB
__device__ __align__(16) __half c_d2ih[3 * H1 * H2];   // 12.6 MB
__device__ __align__(16) __half c_d2hh[3 * H1 * H1];   // 25.2 MB

__device__ __align__(128) unsigned int g_barcnt[32];   // zero-init; self-resetting
__device__ __align__(128) unsigned int g_bargen[32];

// ---------------- helpers -----------------------------------------------------
__device__ __forceinline__ float warp_red(float v) {
    v += __shfl_down_sync(0xffffffffu, v, 16);
    v += __shfl_down_sync(0xffffffffu, v, 8);
    v += __shfl_down_sync(0xffffffffu, v, 4);
    v += __shfl_down_sync(0xffffffffu, v, 2);
    v += __shfl_down_sync(0xffffffffu, v, 1);
    return v;
}

// Software grid barrier; generation-relative so it survives graph replays.
__device__ __forceinline__ void gridsync(int nblk) {
    __threadfence();
    __syncthreads();
    if (threadIdx.x == 0) {
        volatile unsigned int* gen = &g_bargen[0];
        unsigned int g = *gen;
        if (atomicAdd(&g_barcnt[0], 1u) == (unsigned)(nblk - 1)) {
            g_barcnt[0] = 0;
            __threadfence();
            *gen = g + 1;
        } else {
            while (*gen == g) { }
        }
        __threadfence();
    }
    __syncthreads();
}

__device__ __forceinline__ void acc8(float& a, const uint4& r,
                                     const float4& vA, const float4& vB) {
    float2 f;
    f = __half22float2(*reinterpret_cast<const __half2*>(&r.x));
    a = fmaf(f.x, vA.x, a); a = fmaf(f.y, vA.y, a);
    f = __half22float2(*reinterpret_cast<const __half2*>(&r.y));
    a = fmaf(f.x, vA.z, a); a = fmaf(f.y, vA.w, a);
    f = __half22float2(*reinterpret_cast<const __half2*>(&r.z));
    a = fmaf(f.x, vB.x, a); a = fmaf(f.y, vB.y, a);
    f = __half22float2(*reinterpret_cast<const __half2*>(&r.w));
    a = fmaf(f.x, vB.z, a); a = fmaf(f.y, vB.w, a);
}

// 3 simultaneous dot products (r/z/n gate rows, fp16 weights) against an
// fp32 shared-memory vector. Lane-strided: 8 halfs / lane / chunk.
template <int L>
__device__ __forceinline__ void dot3h(const __half* __restrict__ w0,
                                      const __half* __restrict__ w1,
                                      const __half* __restrict__ w2,
                                      const float* __restrict__ sv,
                                      int lane, float& d0, float& d1, float& d2) {
    float a0 = 0.f, a1 = 0.f, a2 = 0.f;
#pragma unroll 2
    for (int j = 0; j < L / 256; ++j) {
        const int idx = j * 256 + lane * 8;
        const float4 vA = *reinterpret_cast<const float4*>(sv + idx);
        const float4 vB = *reinterpret_cast<const float4*>(sv + idx + 4);
        const uint4 r0 = __ldg(reinterpret_cast<const uint4*>(w0 + idx));
        const uint4 r1 = __ldg(reinterpret_cast<const uint4*>(w1 + idx));
        const uint4 r2 = __ldg(reinterpret_cast<const uint4*>(w2 + idx));
        acc8(a0, r0, vA, vB);
        acc8(a1, r1, vA, vB);
        acc8(a2, r2, vA, vB);
    }
    d0 = warp_red(a0);
    d1 = warp_red(a1);
    d2 = warp_red(a2);
}

__device__ __forceinline__ float sigf(float v) { return 1.f / (1.f + expf(-v)); }

// ---------------- fp32 -> fp16 weight conversion ------------------------------
__global__ void f2h_kernel(const float* __restrict__ src, __half* __restrict__ dst, int n) {
    const int stride = gridDim.x * blockDim.x * 8;
    for (int i = (blockIdx.x * blockDim.x + threadIdx.x) * 8; i < n; i += stride) {
        const float4 a = __ldg(reinterpret_cast<const float4*>(src + i));
        const float4 b = __ldg(reinterpret_cast<const float4*>(src + i + 4));
        const __half2 h0 = __floats2half2_rn(a.x, a.y);
        const __half2 h1 = __floats2half2_rn(a.z, a.w);
        const __half2 h2 = __floats2half2_rn(b.x, b.y);
        const __half2 h3 = __floats2half2_rn(b.z, b.w);
        uint4 o;
        o.x = *reinterpret_cast<const unsigned int*>(&h0);
        o.y = *reinterpret_cast<const unsigned int*>(&h1);
        o.z = *reinterpret_cast<const unsigned int*>(&h2);
        o.w = *reinterpret_cast<const unsigned int*>(&h3);
        *reinterpret_cast<uint4*>(dst + i) = o;
    }
}

// ---------------- encoder: e1 (1->2048) + e2 (2048->1024), pipelined ----------
__global__ void __launch_bounds__(NTHR, 1) gru_encoder(
    const float* __restrict__ x,
    const float* __restrict__ w1ih, const float* __restrict__ b1ih,
    const float* __restrict__ b1hh,
    const float* __restrict__ b2ih, const float* __restrict__ b2hh,
    int nblk)
{
    __shared__ __align__(16) float s_h1[H1];   // h1(t-1) == ys1(t-1)
    __shared__ __align__(16) float s_h2[H2];   // h2(t-2)
    const int tid  = threadIdx.x;
    const int lane = tid & 31;
    const int gw   = blockIdx.x * WPB + (tid >> 5);
    const long long NW = (long long)nblk * WPB;

    // Traffic-balanced static partition. Item weights: e1 item = 2 (3x2048 halfs),
    // e2 item = 3 (3x(2048+1024) halfs). Total weight Q = 2048*2 + 1024*3 = 7168.
    const long long Q = 7168;
    int e1lo = (int)(((long long)gw * Q + 2 * NW - 1) / (2 * NW));
    int e1hi = (int)(((long long)(gw + 1) * Q + 2 * NW - 1) / (2 * NW));
    if (e1lo > H1) e1lo = H1;
    if (e1hi > H1) e1hi = H1;
    const long long p0 = (long long)gw * Q - 4096 * NW;
    const long long p1 = (long long)(gw + 1) * Q - 4096 * NW;
    int e2lo = p0 > 0 ? (int)((p0 + 3 * NW - 1) / (3 * NW)) : 0;
    int e2hi = p1 > 0 ? (int)((p1 + 3 * NW - 1) / (3 * NW)) : 0;
    if (e2lo > H2) e2lo = H2;
    if (e2hi > H2) e2hi = H2;

    // Iter t: layer1 computes h1(t) (t<TT); layer2 computes h2(t-1) (t>=1).
    for (int t = 0; t <= TT; ++t) {
        const float* h1p = g_h1[(t + 1) & 1];   // parity of (t-1)
        for (int i = tid * 4; i < H1; i += NTHR * 4) {
            float4 v = (t == 0) ? make_float4(0.f, 0.f, 0.f, 0.f)
                                : __ldcg(reinterpret_cast<const float4*>(h1p + i));
            *reinterpret_cast<float4*>(s_h1 + i) = v;
        }
        const float* h2p = g_h2[t & 1];          // parity of (t-2)
        for (int i = tid * 4; i < H2; i += NTHR * 4) {
            float4 v = (t <= 1) ? make_float4(0.f, 0.f, 0.f, 0.f)
                                : __ldcg(reinterpret_cast<const float4*>(h2p + i));
            *reinterpret_cast<float4*>(s_h2 + i) = v;
        }
        __syncthreads();

        if (t < TT) {
            const float xt = __ldg(x + t);
            for (int i = e1lo; i < e1hi; ++i) {
                float hr, hz, hn;
                dot3h<H1>(c_w1hh + (size_t)i * H1,
                          c_w1hh + (size_t)(i + H1) * H1,
                          c_w1hh + (size_t)(i + 2 * H1) * H1,
                          s_h1, lane, hr, hz, hn);
                if (lane == 0) {
                    const float xr = fmaf(xt, __ldg(w1ih + i),          __ldg(b1ih + i));
                    const float xz = fmaf(xt, __ldg(w1ih + i + H1),     __ldg(b1ih + i + H1));
                    const float xn = fmaf(xt, __ldg(w1ih + i + 2 * H1), __ldg(b1ih + i + 2 * H1));
                    hr += __ldg(b1hh + i);
                    hz += __ldg(b1hh + i + H1);
                    hn += __ldg(b1hh + i + 2 * H1);
                    const float r = sigf(xr + hr);
                    const float z = sigf(xz + hz);
                    const float n = tanhf(xn + r * hn);
                    g_h1[t & 1][i] = (1.f - z) * n + z * s_h1[i];
                }
            }
        }
        if (t >= 1) {
            for (int i = e2lo; i < e2hi; ++i) {     // computing h2(t-1)
                float xr, xz, xn, hr, hz, hn;
                dot3h<H1>(c_w2ih + (size_t)i * H1,
                          c_w2ih + (size_t)(i + H2) * H1,
                          c_w2ih + (size_t)(i + 2 * H2) * H1,
                          s_h1, lane, xr, xz, xn);             // input = ys1(t-1)
                dot3h<H2>(c_w2hh + (size_t)i * H2,
                          c_w2hh + (size_t)(i + H2) * H2,
                          c_w2hh + (size_t)(i + 2 * H2) * H2,
                          s_h2, lane, hr, hz, hn);
                if (lane == 0) {
                    xr += __ldg(b2ih + i);
                    xz += __ldg(b2ih + i + H2);
                    xn += __ldg(b2ih + i + 2 * H2);
                    hr += __ldg(b2hh + i);
                    hz += __ldg(b2hh + i + H2);
                    hn += __ldg(b2hh + i + 2 * H2);
                    const float r = sigf(xr + hr);
                    const float z = sigf(xz + hz);
                    const float n = tanhf(xn + r * hn);
                    g_h2[(t + 1) & 1][i] = (1.f - z) * n + z * s_h2[i]; // parity of (t-1)
                }
            }
        }
        gridsync(nblk);
    }
}

// ---------------- d1 constant input-gate preactivation ------------------------
// emb = final h2 = h2(TT-1), stored at parity (TT-1)&1 == 1.
__global__ void gru_xgd1(const float* __restrict__ d1ih,
                         const float* __restrict__ d1bih)
{
    const int lane = threadIdx.x & 31;
    const int gw = blockIdx.x * (blockDim.x >> 5) + (threadIdx.x >> 5);
    const int nw = gridDim.x * (blockDim.x >> 5);
    for (int j = gw; j < 3 * H2; j += nw) {
        float a = 0.f;
        const float* w = d1ih + (size_t)j * H2;
#pragma unroll 4
        for (int q = 0; q < H2 / 128; ++q) {
            const int idx = q * 128 + lane * 4;
            const float4 r = __ldg(reinterpret_cast<const float4*>(w + idx));
            const float4 v = __ldcg(reinterpret_cast<const float4*>(&g_h2[1][idx]));
            a = fmaf(r.x, v.x, a); a = fmaf(r.y, v.y, a);
            a = fmaf(r.z, v.z, a); a = fmaf(r.w, v.w, a);
        }
        a = warp_red(a);
        if (lane == 0) g_xgd1[j] = a + __ldg(d1bih + j);
    }
}

// ---------------- decoder: d1 (const in ->1024) + d2 (1024->2048), pipelined --
__global__ void __launch_bounds__(NTHR, 1) gru_decoder(
    const float* __restrict__ b1hh,
    const float* __restrict__ b2ih, const float* __restrict__ b2hh,
    int nblk)
{
    __shared__ __align__(16) float s_d1[H2];   // hd1(t-1) == ys2(t-1)
    __shared__ __align__(16) float s_y3[H1];   // ys3(t-2) == hd2 prev state
    const int tid  = threadIdx.x;
    const int lane = tid & 31;
    const int gw   = blockIdx.x * WPB + (tid >> 5);
    const long long NW = (long long)nblk * WPB;

    // Item weights: d1 item = 1 (3x1024 halfs), d2 item = 3 (3x(1024+2048) halfs).
    // Q = 1024*1 + 2048*3 = 7168.
    const long long Q = 7168;
    int d1lo = (int)(((long long)gw * Q + NW - 1) / NW);
    int d1hi = (int)(((long long)(gw + 1) * Q + NW - 1) / NW);
    if (d1lo > H2) d1lo = H2;
    if (d1hi > H2) d1hi = H2;
    const long long p0 = (long long)gw * Q - 1024 * NW;
    const long long p1 = (long long)(gw + 1) * Q - 1024 * NW;
    int d2lo = p0 > 0 ? (int)((p0 + 3 * NW - 1) / (3 * NW)) : 0;
    int d2hi = p1 > 0 ? (int)((p1 + 3 * NW - 1) / (3 * NW)) : 0;
    if (d2lo > H1) d2lo = H1;
    if (d2hi > H1) d2hi = H1;

    for (int t = 0; t <= TT; ++t) {
        const int s = t - 1;                    // d2 computes ys3[s]
        const float* d1p = g_hd1[(t + 1) & 1];
        for (int i = tid * 4; i < H2; i += NTHR * 4) {
            float4 v = (t == 0) ? make_float4(0.f, 0.f, 0.f, 0.f)
                                : __ldcg(reinterpret_cast<const float4*>(d1p + i));
            *reinterpret_cast<float4*>(s_d1 + i) = v;
        }
        for (int i = tid * 4; i < H1; i += NTHR * 4) {
            float4 v = (t <= 1) ? make_float4(0.f, 0.f, 0.f, 0.f)
                                : __ldcg(reinterpret_cast<const float4*>(&g_ys3[s - 1][i]));
            *reinterpret_cast<float4*>(s_y3 + i) = v;
        }
        __syncthreads();

        if (t < TT) {
            for (int i = d1lo; i < d1hi; ++i) {   // d1 output, computing hd1(t)
                float hr, hz, hn;
                dot3h<H2>(c_d1hh + (size_t)i * H2,
                          c_d1hh + (size_t)(i + H2) * H2,
                          c_d1hh + (size_t)(i + 2 * H2) * H2,
                          s_d1, lane, hr, hz, hn);
                if (lane == 0) {
                    const float xr = g_xgd1[i];             // includes bih
                    const float xz = g_xgd1[i + H2];
                    const float xn = g_xgd1[i + 2 * H2];
                    hr += __ldg(b1hh + i);
                    hz += __ldg(b1hh + i + H2);
                    hn += __ldg(b1hh + i + 2 * H2);
                    const float r = sigf(xr + hr);
                    const float z = sigf(xz + hz);
                    const float n = tanhf(xn + r * hn);
                    g_hd1[t & 1][i] = (1.f - z) * n + z * s_d1[i];
                }
            }
        }
        if (t >= 1) {
            for (int i = d2lo; i < d2hi; ++i) {   // d2 output, computing ys3[s]
                float xr, xz, xn, hr, hz, hn;
                dot3h<H2>(c_d2ih + (size_t)i * H2,
                          c_d2ih + (size_t)(i + H1) * H2,
                          c_d2ih + (size_t)(i + 2 * H1) * H2,
                          s_d1, lane, xr, xz, xn);           // input = ys2(s)
                dot3h<H1>(c_d2hh + (size_t)i * H1,
                          c_d2hh + (size_t)(i + H1) * H1,
                          c_d2hh + (size_t)(i + 2 * H1) * H1,
                          s_y3, lane, hr, hz, hn);
                if (lane == 0) {
                    xr += __ldg(b2ih + i);
                    xz += __ldg(b2ih + i + H1);
                    xn += __ldg(b2ih + i + 2 * H1);
                    hr += __ldg(b2hh + i);
                    hz += __ldg(b2hh + i + H1);
                    hn += __ldg(b2hh + i + 2 * H1);
                    const float r = sigf(xr + hr);
                    const float z = sigf(xz + hz);
                    const float n = tanhf(xn + r * hn);
                    g_ys3[s][i] = (1.f - z) * n + z * s_y3[i];
                }
            }
        }
        gridsync(nblk);
    }
}

// ---------------- output head: out[t] = ys3[t] . out_W + out_b ----------------
__global__ void gru_output(const float* __restrict__ ow,
                           const float* __restrict__ ob,
                           float* __restrict__ out)
{
    const int lane = threadIdx.x & 31;
    const int gw = blockIdx.x * (blockDim.x >> 5) + (threadIdx.x >> 5);
    const int nw = gridDim.x * (blockDim.x >> 5);
    for (int t = gw; t < TT; t += nw) {
        float a = 0.f;
#pragma unroll 4
        for (int q = 0; q < H1 / 128; ++q) {
            const int idx = q * 128 + lane * 4;
            const float4 w = __ldg(reinterpret_cast<const float4*>(ow + idx));
            const float4 v = *reinterpret_cast<const float4*>(&g_ys3[t][idx]);
            a = fmaf(w.x, v.x, a); a = fmaf(w.y, v.y, a);
            a = fmaf(w.z, v.z, a); a = fmaf(w.w, v.w, a);
        }
        a = warp_red(a);
        if (lane == 0) out[t] = a + __ldg(ob);
    }
}

// ---------------- launch ------------------------------------------------------
extern "C" void kernel_launch(void* const* d_in, const int* in_sizes, int n_in,
                              void* d_out, int out_size) {
    const float* x      = (const float*)d_in[0];
    const float* e1_Wih = (const float*)d_in[1];
    const float* e1_Whh = (const float*)d_in[2];
    const float* e1_bih = (const float*)d_in[3];
    const float* e1_bhh = (const float*)d_in[4];
    const float* e2_Wih = (const float*)d_in[5];
    const float* e2_Whh = (const float*)d_in[6];
    const float* e2_bih = (const float*)d_in[7];
    const float* e2_bhh = (const float*)d_in[8];
    const float* d1_Wih = (const float*)d_in[9];
    const float* d1_Whh = (const float*)d_in[10];
    const float* d1_bih = (const float*)d_in[11];
    const float* d1_bhh = (const float*)d_in[12];
    const float* d2_Wih = (const float*)d_in[13];
    const float* d2_Whh = (const float*)d_in[14];
    const float* d2_bih = (const float*)d_in[15];
    const float* d2_bhh = (const float*)d_in[16];
    const float* out_W  = (const float*)d_in[17];
    const float* out_b  = (const float*)d_in[18];

    int nblk = 148;
    cudaDeviceGetAttribute(&nblk, cudaDevAttrMultiProcessorCount, 0);

    __half* p_w1hh; cudaGetSymbolAddress((void**)&p_w1hh, c_w1hh);
    __half* p_w2ih; cudaGetSymbolAddress((void**)&p_w2ih, c_w2ih);
    __half* p_w2hh; cudaGetSymbolAddress((void**)&p_w2hh, c_w2hh);
    __half* p_d1hh; cudaGetSymbolAddress((void**)&p_d1hh, c_d1hh);
    __half* p_d2ih; cudaGetSymbolAddress((void**)&p_d2ih, c_d2ih);
    __half* p_d2hh; cudaGetSymbolAddress((void**)&p_d2hh, c_d2hh);

    f2h_kernel<<<512, 256>>>(e1_Whh, p_w1hh, 3 * H1 * H1);
    f2h_kernel<<<512, 256>>>(e2_Wih, p_w2ih, 3 * H2 * H1);
    f2h_kernel<<<512, 256>>>(e2_Whh, p_w2hh, 3 * H2 * H2);
    f2h_kernel<<<512, 256>>>(d1_Whh, p_d1hh, 3 * H2 * H2);
    f2h_kernel<<<512, 256>>>(d2_Wih, p_d2ih, 3 * H1 * H2);
    f2h_kernel<<<512, 256>>>(d2_Whh, p_d2hh, 3 * H1 * H1);

    gru_encoder<<<nblk, NTHR>>>(x, e1_Wih, e1_bih, e1_bhh, e2_bih, e2_bhh, nblk);
    gru_xgd1<<<96, 256>>>(d1_Wih, d1_bih);
    gru_decoder<<<nblk, NTHR>>>(d1_bhh, d2_bih, d2_bhh, nblk);
    gru_output<<<256, 256>>>(out_W, out_b, (float*)d_out);
}

// round 6
// speedup vs baseline: 1.6630x; 1.2304x over previous
#include <cuda_runtime.h>
#include <cuda_fp16.h>

// GRU autoencoder, SEQ_LEN=4096, fp16-compressed streamed weights, fp32 math.
// e1: 1 -> 2048, e2: 2048 -> 1024 (pipelined, 1 grid-sync/step)
// d1: 1024 -> 1024 (constant input => xg precomputed), d2: 1024 -> 2048 (pipelined)
// head: 2048 -> 1
// R5: 512 threads/block (16 warps/SM) + unroll-4 dot products to raise per-SM MLP.

#define TT    4096
#define H1    2048     // e1 / d2 hidden
#define H2    1024     // e2 / d1 hidden
#define NTHR  512
#define WPB   (NTHR >> 5)

// ---------------- device scratch ----------------------------------------------
__device__ float g_h1[2][H1];        // e1 state, double buffered by time parity
__device__ float g_h2[2][H2];        // e2 state
__device__ float g_hd1[2][H2];       // d1 state
__device__ float g_xgd1[3 * H2];     // constant input-gate preactivation for d1
__device__ float g_ys3[TT][H1];      // d2 outputs (also d2 state history)

// fp16 copies of the streamed weight matrices (converted on every launch)
__device__ __align__(16) __half c_w1hh[3 * H1 * H1];   // 25.2 MB
__device__ __align__(16) __half c_w2ih[3 * H2 * H1];   // 12.6 MB
__device__ __align__(16) __half c_w2hh[3 * H2 * H2];   //  6.3 MB
__device__ __align__(16) __half c_d1hh[3 * H2 * H2];   //  6.3 MB
__device__ __align__(16) __half c_d2ih[3 * H1 * H2];   // 12.6 MB
__device__ __align__(16) __half c_d2hh[3 * H1 * H1];   // 25.2 MB

__device__ __align__(128) unsigned int g_barcnt[32];   // zero-init; self-resetting
__device__ __align__(128) unsigned int g_bargen[32];

// ---------------- helpers -----------------------------------------------------
__device__ __forceinline__ float warp_red(float v) {
    v += __shfl_down_sync(0xffffffffu, v, 16);
    v += __shfl_down_sync(0xffffffffu, v, 8);
    v += __shfl_down_sync(0xffffffffu, v, 4);
    v += __shfl_down_sync(0xffffffffu, v, 2);
    v += __shfl_down_sync(0xffffffffu, v, 1);
    return v;
}

// Software grid barrier; generation-relative so it survives graph replays.
__device__ __forceinline__ void gridsync(int nblk) {
    __threadfence();
    __syncthreads();
    if (threadIdx.x == 0) {
        volatile unsigned int* gen = &g_bargen[0];
        unsigned int g = *gen;
        if (atomicAdd(&g_barcnt[0], 1u) == (unsigned)(nblk - 1)) {
            g_barcnt[0] = 0;
            __threadfence();
            *gen = g + 1;
        } else {
            while (*gen == g) { }
        }
        __threadfence();
    }
    __syncthreads();
}

__device__ __forceinline__ void acc8(float& a, const uint4& r,
                                     const float4& vA, const float4& vB) {
    float2 f;
    f = __half22float2(*reinterpret_cast<const __half2*>(&r.x));
    a = fmaf(f.x, vA.x, a); a = fmaf(f.y, vA.y, a);
    f = __half22float2(*reinterpret_cast<const __half2*>(&r.y));
    a = fmaf(f.x, vA.z, a); a = fmaf(f.y, vA.w, a);
    f = __half22float2(*reinterpret_cast<const __half2*>(&r.z));
    a = fmaf(f.x, vB.x, a); a = fmaf(f.y, vB.y, a);
    f = __half22float2(*reinterpret_cast<const __half2*>(&r.w));
    a = fmaf(f.x, vB.z, a); a = fmaf(f.y, vB.w, a);
}

// 3 simultaneous dot products (r/z/n gate rows, fp16 weights) against an
// fp32 shared-memory vector. Lane-strided: 8 halfs / lane / chunk.
// Unroll 4 => up to 12 LDG.128 batched per warp to cover L2 latency.
template <int L>
__device__ __forceinline__ void dot3h(const __half* __restrict__ w0,
                                      const __half* __restrict__ w1,
                                      const __half* __restrict__ w2,
                                      const float* __restrict__ sv,
                                      int lane, float& d0, float& d1, float& d2) {
    float a0 = 0.f, a1 = 0.f, a2 = 0.f;
#pragma unroll 4
    for (int j = 0; j < L / 256; ++j) {
        const int idx = j * 256 + lane * 8;
        const uint4 r0 = __ldg(reinterpret_cast<const uint4*>(w0 + idx));
        const uint4 r1 = __ldg(reinterpret_cast<const uint4*>(w1 + idx));
        const uint4 r2 = __ldg(reinterpret_cast<const uint4*>(w2 + idx));
        const float4 vA = *reinterpret_cast<const float4*>(sv + idx);
        const float4 vB = *reinterpret_cast<const float4*>(sv + idx + 4);
        acc8(a0, r0, vA, vB);
        acc8(a1, r1, vA, vB);
        acc8(a2, r2, vA, vB);
    }
    d0 = warp_red(a0);
    d1 = warp_red(a1);
    d2 = warp_red(a2);
}

__device__ __forceinline__ float sigf(float v) { return 1.f / (1.f + expf(-v)); }

// ---------------- fp32 -> fp16 weight conversion ------------------------------
__global__ void f2h_kernel(const float* __restrict__ src, __half* __restrict__ dst, int n) {
    const int stride = gridDim.x * blockDim.x * 8;
    for (int i = (blockIdx.x * blockDim.x + threadIdx.x) * 8; i < n; i += stride) {
        const float4 a = __ldg(reinterpret_cast<const float4*>(src + i));
        const float4 b = __ldg(reinterpret_cast<const float4*>(src + i + 4));
        const __half2 h0 = __floats2half2_rn(a.x, a.y);
        const __half2 h1 = __floats2half2_rn(a.z, a.w);
        const __half2 h2 = __floats2half2_rn(b.x, b.y);
        const __half2 h3 = __floats2half2_rn(b.z, b.w);
        uint4 o;
        o.x = *reinterpret_cast<const unsigned int*>(&h0);
        o.y = *reinterpret_cast<const unsigned int*>(&h1);
        o.z = *reinterpret_cast<const unsigned int*>(&h2);
        o.w = *reinterpret_cast<const unsigned int*>(&h3);
        *reinterpret_cast<uint4*>(dst + i) = o;
    }
}

// ---------------- encoder: e1 (1->2048) + e2 (2048->1024), pipelined ----------
__global__ void __launch_bounds__(NTHR, 1) gru_encoder(
    const float* __restrict__ x,
    const float* __restrict__ w1ih, const float* __restrict__ b1ih,
    const float* __restrict__ b1hh,
    const float* __restrict__ b2ih, const float* __restrict__ b2hh,
    int nblk)
{
    __shared__ __align__(16) float s_h1[H1];   // h1(t-1) == ys1(t-1)
    __shared__ __align__(16) float s_h2[H2];   // h2(t-2)
    const int tid  = threadIdx.x;
    const int lane = tid & 31;
    const int gw   = blockIdx.x * WPB + (tid >> 5);
    const long long NW = (long long)nblk * WPB;

    // Traffic-balanced static partition. Item weights: e1 item = 2 (3x2048 halfs),
    // e2 item = 3 (3x(2048+1024) halfs). Total weight Q = 2048*2 + 1024*3 = 7168.
    const long long Q = 7168;
    int e1lo = (int)(((long long)gw * Q + 2 * NW - 1) / (2 * NW));
    int e1hi = (int)(((long long)(gw + 1) * Q + 2 * NW - 1) / (2 * NW));
    if (e1lo > H1) e1lo = H1;
    if (e1hi > H1) e1hi = H1;
    const long long p0 = (long long)gw * Q - 4096 * NW;
    const long long p1 = (long long)(gw + 1) * Q - 4096 * NW;
    int e2lo = p0 > 0 ? (int)((p0 + 3 * NW - 1) / (3 * NW)) : 0;
    int e2hi = p1 > 0 ? (int)((p1 + 3 * NW - 1) / (3 * NW)) : 0;
    if (e2lo > H2) e2lo = H2;
    if (e2hi > H2) e2hi = H2;

    // Iter t: layer1 computes h1(t) (t<TT); layer2 computes h2(t-1) (t>=1).
    for (int t = 0; t <= TT; ++t) {
        const float* h1p = g_h1[(t + 1) & 1];   // parity of (t-1)
        for (int i = tid * 4; i < H1; i += NTHR * 4) {
            float4 v = (t == 0) ? make_float4(0.f, 0.f, 0.f, 0.f)
                                : __ldcg(reinterpret_cast<const float4*>(h1p + i));
            *reinterpret_cast<float4*>(s_h1 + i) = v;
        }
        const float* h2p = g_h2[t & 1];          // parity of (t-2)
        for (int i = tid * 4; i < H2; i += NTHR * 4) {
            float4 v = (t <= 1) ? make_float4(0.f, 0.f, 0.f, 0.f)
                                : __ldcg(reinterpret_cast<const float4*>(h2p + i));
            *reinterpret_cast<float4*>(s_h2 + i) = v;
        }
        __syncthreads();

        if (t < TT) {
            const float xt = __ldg(x + t);
            for (int i = e1lo; i < e1hi; ++i) {
                float hr, hz, hn;
                dot3h<H1>(c_w1hh + (size_t)i * H1,
                          c_w1hh + (size_t)(i + H1) * H1,
                          c_w1hh + (size_t)(i + 2 * H1) * H1,
                          s_h1, lane, hr, hz, hn);
                if (lane == 0) {
                    const float xr = fmaf(xt, __ldg(w1ih + i),          __ldg(b1ih + i));
                    const float xz = fmaf(xt, __ldg(w1ih + i + H1),     __ldg(b1ih + i + H1));
                    const float xn = fmaf(xt, __ldg(w1ih + i + 2 * H1), __ldg(b1ih + i + 2 * H1));
                    hr += __ldg(b1hh + i);
                    hz += __ldg(b1hh + i + H1);
                    hn += __ldg(b1hh + i + 2 * H1);
                    const float r = sigf(xr + hr);
                    const float z = sigf(xz + hz);
                    const float n = tanhf(xn + r * hn);
                    g_h1[t & 1][i] = (1.f - z) * n + z * s_h1[i];
                }
            }
        }
        if (t >= 1) {
            for (int i = e2lo; i < e2hi; ++i) {     // computing h2(t-1)
                float xr, xz, xn, hr, hz, hn;
                dot3h<H1>(c_w2ih + (size_t)i * H1,
                          c_w2ih + (size_t)(i + H2) * H1,
                          c_w2ih + (size_t)(i + 2 * H2) * H1,
                          s_h1, lane, xr, xz, xn);             // input = ys1(t-1)
                dot3h<H2>(c_w2hh + (size_t)i * H2,
                          c_w2hh + (size_t)(i + H2) * H2,
                          c_w2hh + (size_t)(i + 2 * H2) * H2,
                          s_h2, lane, hr, hz, hn);
                if (lane == 0) {
                    xr += __ldg(b2ih + i);
                    xz += __ldg(b2ih + i + H2);
                    xn += __ldg(b2ih + i + 2 * H2);
                    hr += __ldg(b2hh + i);
                    hz += __ldg(b2hh + i + H2);
                    hn += __ldg(b2hh + i + 2 * H2);
                    const float r = sigf(xr + hr);
                    const float z = sigf(xz + hz);
                    const float n = tanhf(xn + r * hn);
                    g_h2[(t + 1) & 1][i] = (1.f - z) * n + z * s_h2[i]; // parity of (t-1)
                }
            }
        }
        gridsync(nblk);
    }
}

// ---------------- d1 constant input-gate preactivation ------------------------
// emb = final h2 = h2(TT-1), stored at parity (TT-1)&1 == 1.
__global__ void gru_xgd1(const float* __restrict__ d1ih,
                         const float* __restrict__ d1bih)
{
    const int lane = threadIdx.x & 31;
    const int gw = blockIdx.x * (blockDim.x >> 5) + (threadIdx.x >> 5);
    const int nw = gridDim.x * (blockDim.x >> 5);
    for (int j = gw; j < 3 * H2; j += nw) {
        float a = 0.f;
        const float* w = d1ih + (size_t)j * H2;
#pragma unroll 4
        for (int q = 0; q < H2 / 128; ++q) {
            const int idx = q * 128 + lane * 4;
            const float4 r = __ldg(reinterpret_cast<const float4*>(w + idx));
            const float4 v = __ldcg(reinterpret_cast<const float4*>(&g_h2[1][idx]));
            a = fmaf(r.x, v.x, a); a = fmaf(r.y, v.y, a);
            a = fmaf(r.z, v.z, a); a = fmaf(r.w, v.w, a);
        }
        a = warp_red(a);
        if (lane == 0) g_xgd1[j] = a + __ldg(d1bih + j);
    }
}

// ---------------- decoder: d1 (const in ->1024) + d2 (1024->2048), pipelined --
__global__ void __launch_bounds__(NTHR, 1) gru_decoder(
    const float* __restrict__ b1hh,
    const float* __restrict__ b2ih, const float* __restrict__ b2hh,
    int nblk)
{
    __shared__ __align__(16) float s_d1[H2];   // hd1(t-1) == ys2(t-1)
    __shared__ __align__(16) float s_y3[H1];   // ys3(t-2) == hd2 prev state
    const int tid  = threadIdx.x;
    const int lane = tid & 31;
    const int gw   = blockIdx.x * WPB + (tid >> 5);
    const long long NW = (long long)nblk * WPB;

    // Item weights: d1 item = 1 (3x1024 halfs), d2 item = 3 (3x(1024+2048) halfs).
    // Q = 1024*1 + 2048*3 = 7168.
    const long long Q = 7168;
    int d1lo = (int)(((long long)gw * Q + NW - 1) / NW);
    int d1hi = (int)(((long long)(gw + 1) * Q + NW - 1) / NW);
    if (d1lo > H2) d1lo = H2;
    if (d1hi > H2) d1hi = H2;
    const long long p0 = (long long)gw * Q - 1024 * NW;
    const long long p1 = (long long)(gw + 1) * Q - 1024 * NW;
    int d2lo = p0 > 0 ? (int)((p0 + 3 * NW - 1) / (3 * NW)) : 0;
    int d2hi = p1 > 0 ? (int)((p1 + 3 * NW - 1) / (3 * NW)) : 0;
    if (d2lo > H1) d2lo = H1;
    if (d2hi > H1) d2hi = H1;

    for (int t = 0; t <= TT; ++t) {
        const int s = t - 1;                    // d2 computes ys3[s]
        const float* d1p = g_hd1[(t + 1) & 1];
        for (int i = tid * 4; i < H2; i += NTHR * 4) {
            float4 v = (t == 0) ? make_float4(0.f, 0.f, 0.f, 0.f)
                                : __ldcg(reinterpret_cast<const float4*>(d1p + i));
            *reinterpret_cast<float4*>(s_d1 + i) = v;
        }
        for (int i = tid * 4; i < H1; i += NTHR * 4) {
            float4 v = (t <= 1) ? make_float4(0.f, 0.f, 0.f, 0.f)
                                : __ldcg(reinterpret_cast<const float4*>(&g_ys3[s - 1][i]));
            *reinterpret_cast<float4*>(s_y3 + i) = v;
        }
        __syncthreads();

        if (t < TT) {
            for (int i = d1lo; i < d1hi; ++i) {   // d1 output, computing hd1(t)
                float hr, hz, hn;
                dot3h<H2>(c_d1hh + (size_t)i * H2,
                          c_d1hh + (size_t)(i + H2) * H2,
                          c_d1hh + (size_t)(i + 2 * H2) * H2,
                          s_d1, lane, hr, hz, hn);
                if (lane == 0) {
                    const float xr = g_xgd1[i];             // includes bih
                    const float xz = g_xgd1[i + H2];
                    const float xn = g_xgd1[i + 2 * H2];
                    hr += __ldg(b1hh + i);
                    hz += __ldg(b1hh + i + H2);
                    hn += __ldg(b1hh + i + 2 * H2);
                    const float r = sigf(xr + hr);
                    const float z = sigf(xz + hz);
                    const float n = tanhf(xn + r * hn);
                    g_hd1[t & 1][i] = (1.f - z) * n + z * s_d1[i];
                }
            }
        }
        if (t >= 1) {
            for (int i = d2lo; i < d2hi; ++i) {   // d2 output, computing ys3[s]
                float xr, xz, xn, hr, hz, hn;
                dot3h<H2>(c_d2ih + (size_t)i * H2,
                          c_d2ih + (size_t)(i + H1) * H2,
                          c_d2ih + (size_t)(i + 2 * H1) * H2,
                          s_d1, lane, xr, xz, xn);           // input = ys2(s)
                dot3h<H1>(c_d2hh + (size_t)i * H1,
                          c_d2hh + (size_t)(i + H1) * H1,
                          c_d2hh + (size_t)(i + 2 * H1) * H1,
                          s_y3, lane, hr, hz, hn);
                if (lane == 0) {
                    xr += __ldg(b2ih + i);
                    xz += __ldg(b2ih + i + H1);
                    xn += __ldg(b2ih + i + 2 * H1);
                    hr += __ldg(b2hh + i);
                    hz += __ldg(b2hh + i + H1);
                    hn += __ldg(b2hh + i + 2 * H1);
                    const float r = sigf(xr + hr);
                    const float z = sigf(xz + hz);
                    const float n = tanhf(xn + r * hn);
                    g_ys3[s][i] = (1.f - z) * n + z * s_y3[i];
                }
            }
        }
        gridsync(nblk);
    }
}

// ---------------- output head: out[t] = ys3[t] . out_W + out_b ----------------
__global__ void gru_output(const float* __restrict__ ow,
                           const float* __restrict__ ob,
                           float* __restrict__ out)
{
    const int lane = threadIdx.x & 31;
    const int gw = blockIdx.x * (blockDim.x >> 5) + (threadIdx.x >> 5);
    const int nw = gridDim.x * (blockDim.x >> 5);
    for (int t = gw; t < TT; t += nw) {
        float a = 0.f;
#pragma unroll 4
        for (int q = 0; q < H1 / 128; ++q) {
            const int idx = q * 128 + lane * 4;
            const float4 w = __ldg(reinterpret_cast<const float4*>(ow + idx));
            const float4 v = *reinterpret_cast<const float4*>(&g_ys3[t][idx]);
            a = fmaf(w.x, v.x, a); a = fmaf(w.y, v.y, a);
            a = fmaf(w.z, v.z, a); a = fmaf(w.w, v.w, a);
        }
        a = warp_red(a);
        if (lane == 0) out[t] = a + __ldg(ob);
    }
}

// ---------------- launch ------------------------------------------------------
extern "C" void kernel_launch(void* const* d_in, const int* in_sizes, int n_in,
                              void* d_out, int out_size) {
    const float* x      = (const float*)d_in[0];
    const float* e1_Wih = (const float*)d_in[1];
    const float* e1_Whh = (const float*)d_in[2];
    const float* e1_bih = (const float*)d_in[3];
    const float* e1_bhh = (const float*)d_in[4];
    const float* e2_Wih = (const float*)d_in[5];
    const float* e2_Whh = (const float*)d_in[6];
    const float* e2_bih = (const float*)d_in[7];
    const float* e2_bhh = (const float*)d_in[8];
    const float* d1_Wih = (const float*)d_in[9];
    const float* d1_Whh = (const float*)d_in[10];
    const float* d1_bih = (const float*)d_in[11];
    const float* d1_bhh = (const float*)d_in[12];
    const float* d2_Wih = (const float*)d_in[13];
    const float* d2_Whh = (const float*)d_in[14];
    const float* d2_bih = (const float*)d_in[15];
    const float* d2_bhh = (const float*)d_in[16];
    const float* out_W  = (const float*)d_in[17];
    const float* out_b  = (const float*)d_in[18];

    int nblk = 148;
    cudaDeviceGetAttribute(&nblk, cudaDevAttrMultiProcessorCount, 0);

    __half* p_w1hh; cudaGetSymbolAddress((void**)&p_w1hh, c_w1hh);
    __half* p_w2ih; cudaGetSymbolAddress((void**)&p_w2ih, c_w2ih);
    __half* p_w2hh; cudaGetSymbolAddress((void**)&p_w2hh, c_w2hh);
    __half* p_d1hh; cudaGetSymbolAddress((void**)&p_d1hh, c_d1hh);
    __half* p_d2ih; cudaGetSymbolAddress((void**)&p_d2ih, c_d2ih);
    __half* p_d2hh; cudaGetSymbolAddress((void**)&p_d2hh, c_d2hh);

    f2h_kernel<<<512, 256>>>(e1_Whh, p_w1hh, 3 * H1 * H1);
    f2h_kernel<<<512, 256>>>(e2_Wih, p_w2ih, 3 * H2 * H1);
    f2h_kernel<<<512, 256>>>(e2_Whh, p_w2hh, 3 * H2 * H2);
    f2h_kernel<<<512, 256>>>(d1_Whh, p_d1hh, 3 * H2 * H2);
    f2h_kernel<<<512, 256>>>(d2_Wih, p_d2ih, 3 * H1 * H2);
    f2h_kernel<<<512, 256>>>(d2_Whh, p_d2hh, 3 * H1 * H1);

    gru_encoder<<<nblk, NTHR>>>(x, e1_Wih, e1_bih, e1_bhh, e2_bih, e2_bhh, nblk);
    gru_xgd1<<<96, 256>>>(d1_Wih, d1_bih);
    gru_decoder<<<nblk, NTHR>>>(d1_bhh, d2_bih, d2_bhh, nblk);
    gru_output<<<256, 256>>>(out_W, out_b, (float*)d_out);
}